// round 8
// baseline (speedup 1.0000x reference)
#include <cuda_runtime.h>
#include <math.h>

// ============================================================================
// QuanvolutionFilter via fixed-unitary reduction + monomial (double-angle)
// basis; 4 patches/thread as two f32x2 lane-pairs; coefficients split
// between __constant__ (even slots, LDC port) and shared memory (odd slots,
// LDS port) so neither port binds below the FMA-pipe floor.
//
//   out_k(patch) = sum_{u,v} D_k[u][v] * m01[u] * m23[v]
//   m01 = {1,C0,S0}x{1,C1,S1}, m23 = {1,C2,S2}x{1,C3,S3}
// ============================================================================

#define PACK_F32X2(out, lo, hi) \
    asm("mov.b64 %0, {%1, %2};" : "=l"(out) : "f"(lo), "f"(hi))
#define UNPACK_F32X2(lo, hi, in) \
    asm("mov.b64 {%0, %1}, %2;" : "=f"(lo), "=f"(hi) : "l"(in))
#define MUL_F32X2(out, a, b) \
    asm("mul.rn.f32x2 %0, %1, %2;" : "=l"(out) : "l"(a), "l"(b))
#define FMA_F32X2(d, a, b, c) \
    asm("fma.rn.f32x2 %0, %1, %2, %3;" : "=l"(d) : "l"(a), "l"(b), "l"(c))

// coefficient slot (u*9+v): two float4 = (D0,D0,D1,D1),(D2,D2,D3,D3)
__device__ __align__(16) float g_D[81 * 8];
__constant__ ulonglong2 cD[162];

__device__ __forceinline__ float Ecoef(int f, int fp, int al) {
    if (al == 2) return (f != fp) ? 0.5f : 0.0f;   // cs -> sin(a)/2
    if (f != fp) return 0.0f;
    if (al == 0) return 0.5f;                       // cc,ss -> 1/2
    return f ? -0.5f : 0.5f;                        // cc -> +cos/2, ss -> -cos/2
}

__global__ void qsetup(const float* __restrict__ params,   // (3,4,3)
                       const float* __restrict__ W,        // (4,4)
                       const float* __restrict__ bvec)     // (4,)
{
    __shared__ float Ur[16][17];
    __shared__ float Ui[16][17];
    __shared__ float sG[12][8];
    __shared__ float sA[4][16][16];
    __shared__ float sS[4][4][4][9];
    __shared__ float sDt[4][9][9];

    const int t = threadIdx.x;
    const int n = t >> 4, c = t & 15;

    if (t < 12) {
        float phi = params[t * 3 + 0];
        float th  = params[t * 3 + 1];
        float om  = params[t * 3 + 2];
        float ct = cosf(0.5f * th), st = sinf(0.5f * th);
        float a  = 0.5f * (phi + om);
        float bb = 0.5f * (phi - om);
        float ca = cosf(a),  sa = sinf(a);
        float cb = cosf(bb), sb = sinf(bb);
        sG[t][0] =  ca * ct;  sG[t][1] = -sa * ct;
        sG[t][2] = -cb * st;  sG[t][3] = -sb * st;
        sG[t][4] =  cb * st;  sG[t][5] = -sb * st;
        sG[t][6] =  ca * ct;  sG[t][7] =  sa * ct;
    }
    Ur[n][c] = (n == c) ? 1.0f : 0.0f;
    Ui[n][c] = 0.0f;
    __syncthreads();

    #pragma unroll
    for (int l = 0; l < 3; ++l) {
        #pragma unroll
        for (int w = 0; w < 4; ++w) {
            const int mask = 8 >> w;
            const float* g = sG[l * 4 + w];
            float xr = Ur[n][c], xi = Ui[n][c];
            float yr = Ur[n ^ mask][c], yi = Ui[n ^ mask][c];
            float nr, ni;
            if (!(n & mask)) {
                nr = g[0]*xr - g[1]*xi + g[2]*yr - g[3]*yi;
                ni = g[0]*xi + g[1]*xr + g[2]*yi + g[3]*yr;
            } else {
                nr = g[4]*yr - g[5]*yi + g[6]*xr - g[7]*xi;
                ni = g[4]*yi + g[5]*yr + g[6]*xi + g[7]*xr;
            }
            __syncthreads();
            Ur[n][c] = nr; Ui[n][c] = ni;
            __syncthreads();
        }
        const int r = (l % 3) + 1;
        int m = n;
        #pragma unroll
        for (int w = 3; w >= 0; --w) {
            const int cm = 8 >> w, tm = 8 >> ((w + r) & 3);
            if (m & cm) m ^= tm;
        }
        float vr = Ur[m][c], vi = Ui[m][c];
        __syncthreads();
        Ur[n][c] = vr; Ui[n][c] = vi;
        __syncthreads();
    }

    {
        const int i = n, j = c;
        float M[4] = {0.f, 0.f, 0.f, 0.f};
        #pragma unroll
        for (int nn = 0; nn < 16; ++nn) {
            float v = Ur[nn][i] * Ur[nn][j] + Ui[nn][i] * Ui[nn][j];
            #pragma unroll
            for (int w = 0; w < 4; ++w)
                M[w] += (nn & (8 >> w)) ? -v : v;
        }
        #pragma unroll
        for (int k = 0; k < 4; ++k) {
            float acc = 0.0f;
            #pragma unroll
            for (int w = 0; w < 4; ++w) acc += W[k * 4 + w] * M[w];
            sA[k][i][j] = acc;
        }
    }
    __syncthreads();

    for (int idx = t; idx < 576; idx += 256) {
        int k   = idx / 144;
        int rem = idx - k * 144;
        int i01 = rem / 36;
        int r2  = rem - i01 * 36;
        int j01 = r2 / 9;
        int v   = r2 - j01 * 9;
        int a2 = v / 3, a3 = v - a2 * 3;
        float acc = 0.0f;
        #pragma unroll
        for (int i23 = 0; i23 < 4; ++i23)
            #pragma unroll
            for (int j23 = 0; j23 < 4; ++j23) {
                float e = Ecoef(i23 >> 1, j23 >> 1, a2) * Ecoef(i23 & 1, j23 & 1, a3);
                acc += e * sA[k][i01 * 4 + i23][j01 * 4 + j23];
            }
        sS[k][i01][j01][v] = acc;
    }
    __syncthreads();

    for (int idx = t; idx < 324; idx += 256) {
        int k  = idx / 81;
        int uv = idx - k * 81;
        int u  = uv / 9;
        int v  = uv - u * 9;
        int a0 = u / 3, a1 = u - a0 * 3;
        float acc = 0.0f;
        #pragma unroll
        for (int i01 = 0; i01 < 4; ++i01)
            #pragma unroll
            for (int j01 = 0; j01 < 4; ++j01) {
                float e = Ecoef(i01 >> 1, j01 >> 1, a0) * Ecoef(i01 & 1, j01 & 1, a1);
                acc += e * sS[k][i01][j01][v];
            }
        if (u == 0 && v == 0) acc += bvec[k];
        sDt[k][u][v] = acc;
    }
    __syncthreads();

    if (t < 81) {
        int u = t / 9, v = t - u * 9;
        float4* gd = reinterpret_cast<float4*>(g_D);
        gd[t * 2 + 0] = make_float4(sDt[0][u][v], sDt[0][u][v],
                                    sDt[1][u][v], sDt[1][u][v]);
        gd[t * 2 + 1] = make_float4(sDt[2][u][v], sDt[2][u][v],
                                    sDt[3][u][v], sDt[3][u][v]);
    }
}

__device__ __forceinline__ void patch_angles(const float* __restrict__ x, int gid,
                                             float* C, float* S)
{
    int b  = gid / 196;
    int p  = gid - b * 196;
    int pr = p / 14;
    int pc = p - pr * 14;
    const float* img = x + b * 784 + pr * 56 + pc * 2;
    float2 r0 = *reinterpret_cast<const float2*>(img);
    float2 r1 = *reinterpret_cast<const float2*>(img + 28);
    __sincosf(r0.x, &S[0], &C[0]);
    __sincosf(r0.y, &S[1], &C[1]);
    __sincosf(r1.x, &S[2], &C[2]);
    __sincosf(r1.y, &S[3], &C[3]);
}

// build the 8 non-unit m23 monomials for one patch
__device__ __forceinline__ void m23_vals(const float* C, const float* S, float* mv)
{
    mv[0] = C[3];        mv[1] = S[3];
    mv[2] = C[2];        mv[3] = C[2] * C[3];
    mv[4] = C[2] * S[3]; mv[5] = S[2];
    mv[6] = S[2] * C[3]; mv[7] = S[2] * S[3];
}

__global__ void __launch_bounds__(256, 3) qmain(const float* __restrict__ x,
                                                float* __restrict__ out,
                                                int quarter, int total)
{
    __shared__ ulonglong2 sD[162];
    for (int i = threadIdx.x; i < 162; i += 256)
        sD[i] = reinterpret_cast<const ulonglong2*>(g_D)[i];
    __syncthreads();

    int g0 = blockIdx.x * blockDim.x + threadIdx.x;
    if (g0 >= quarter) return;
    int g1 = g0 + quarter;
    int g2 = g0 + 2 * quarter;
    int g3 = g0 + 3 * quarter;
    bool h1 = (g1 < total), h2 = (g2 < total), h3 = (g3 < total);

    float C[4][4], S[4][4];                 // [patch][wire]
    patch_angles(x, g0, C[0], S[0]);
    patch_angles(x, h1 ? g1 : g0, C[1], S[1]);
    patch_angles(x, h2 ? g2 : g0, C[2], S[2]);
    patch_angles(x, h3 ? g3 : g0, C[3], S[3]);

    // lane-pair A = (patch0, patch1), lane-pair B = (patch2, patch3)
    unsigned long long f0cA, f0sA, f1cA, f1sA;
    unsigned long long f0cB, f0sB, f1cB, f1sB;
    PACK_F32X2(f0cA, C[0][0], C[1][0]);  PACK_F32X2(f0cB, C[2][0], C[3][0]);
    PACK_F32X2(f0sA, S[0][0], S[1][0]);  PACK_F32X2(f0sB, S[2][0], S[3][0]);
    PACK_F32X2(f1cA, C[0][1], C[1][1]);  PACK_F32X2(f1cB, C[2][1], C[3][1]);
    PACK_F32X2(f1sA, S[0][1], S[1][1]);  PACK_F32X2(f1sB, S[2][1], S[3][1]);

    unsigned long long m23A[8], m23B[8];
    {
        float v0[8], v1[8], v2[8], v3[8];
        m23_vals(C[0], S[0], v0);
        m23_vals(C[1], S[1], v1);
        m23_vals(C[2], S[2], v2);
        m23_vals(C[3], S[3], v3);
        #pragma unroll
        for (int v = 0; v < 8; ++v) {
            PACK_F32X2(m23A[v], v0[v], v1[v]);
            PACK_F32X2(m23B[v], v2[v], v3[v]);
        }
    }

    // acc init = D[0][0] (bias folded), since tp(0,0) = 1
    unsigned long long aA0, aA1, aA2, aA3, aB0, aB1, aB2, aB3;
    {
        ulonglong2 w0 = cD[0], w1 = cD[1];
        aA0 = w0.x; aA1 = w0.y; aA2 = w1.x; aA3 = w1.y;
        aB0 = w0.x; aB1 = w0.y; aB2 = w1.x; aB3 = w1.y;
    }

    #pragma unroll
    for (int u = 0; u < 9; ++u) {
        unsigned long long mA = 0, mB = 0;
        if      (u == 1) { mA = f1cA; mB = f1cB; }
        else if (u == 2) { mA = f1sA; mB = f1sB; }
        else if (u == 3) { mA = f0cA; mB = f0cB; }
        else if (u == 4) { MUL_F32X2(mA, f0cA, f1cA); MUL_F32X2(mB, f0cB, f1cB); }
        else if (u == 5) { MUL_F32X2(mA, f0cA, f1sA); MUL_F32X2(mB, f0cB, f1sB); }
        else if (u == 6) { mA = f0sA; mB = f0sB; }
        else if (u == 7) { MUL_F32X2(mA, f0sA, f1cA); MUL_F32X2(mB, f0sB, f1cB); }
        else if (u == 8) { MUL_F32X2(mA, f0sA, f1sA); MUL_F32X2(mB, f0sB, f1sB); }

        #pragma unroll
        for (int v = 0; v < 9; ++v) {
            if (u == 0 && v == 0) continue;
            const int s = u * 9 + v;
            ulonglong2 wa, wb;
            if (s & 1) { wa = sD[s * 2 + 0]; wb = sD[s * 2 + 1]; }
            else       { wa = cD[s * 2 + 0]; wb = cD[s * 2 + 1]; }

            unsigned long long tA, tB;
            if (u == 0)      { tA = m23A[v - 1]; tB = m23B[v - 1]; }
            else if (v == 0) { tA = mA;          tB = mB; }
            else { MUL_F32X2(tA, mA, m23A[v - 1]); MUL_F32X2(tB, mB, m23B[v - 1]); }

            FMA_F32X2(aA0, wa.x, tA, aA0);
            FMA_F32X2(aB0, wa.x, tB, aB0);
            FMA_F32X2(aA1, wa.y, tA, aA1);
            FMA_F32X2(aB1, wa.y, tB, aB1);
            FMA_F32X2(aA2, wb.x, tA, aA2);
            FMA_F32X2(aB2, wb.x, tB, aB2);
            FMA_F32X2(aA3, wb.y, tA, aA3);
            FMA_F32X2(aB3, wb.y, tB, aB3);
        }
    }

    float p0, q0, p1, q1, p2, q2, p3, q3;
    UNPACK_F32X2(p0, q0, aA0);
    UNPACK_F32X2(p1, q1, aA1);
    UNPACK_F32X2(p2, q2, aA2);
    UNPACK_F32X2(p3, q3, aA3);
    reinterpret_cast<float4*>(out)[g0] = make_float4(p0, p1, p2, p3);
    if (h1) reinterpret_cast<float4*>(out)[g1] = make_float4(q0, q1, q2, q3);

    UNPACK_F32X2(p0, q0, aB0);
    UNPACK_F32X2(p1, q1, aB1);
    UNPACK_F32X2(p2, q2, aB2);
    UNPACK_F32X2(p3, q3, aB3);
    if (h2) reinterpret_cast<float4*>(out)[g2] = make_float4(p0, p1, p2, p3);
    if (h3) reinterpret_cast<float4*>(out)[g3] = make_float4(q0, q1, q2, q3);
}

extern "C" void kernel_launch(void* const* d_in, const int* in_sizes, int n_in,
                              void* d_out, int out_size)
{
    const float* x      = (const float*)d_in[0];   // (B,1,28,28)
    const float* params = (const float*)d_in[1];   // (3,4,3)
    const float* W      = (const float*)d_in[2];   // (4,4)
    const float* bvec   = (const float*)d_in[3];   // (4,)
    float* out = (float*)d_out;                    // (B, 784)

    int total   = in_sizes[0] / 4;                 // B*196 patches
    int quarter = (total + 3) / 4;

    qsetup<<<1, 256>>>(params, W, bvec);

    // stage device-computed coefficients into constant memory (D2D, capturable)
    void* gptr = nullptr;
    cudaGetSymbolAddress(&gptr, g_D);
    cudaMemcpyToSymbolAsync(cD, gptr, sizeof(float) * 81 * 8, 0,
                            cudaMemcpyDeviceToDevice, 0);

    qmain<<<(quarter + 255) / 256, 256>>>(x, out, quarter, total);
}